// round 2
// baseline (speedup 1.0000x reference)
#include <cuda_runtime.h>
#include <math.h>

#define M_    8
#define B_    64
#define S_    128
#define D_    512
#define H_    8
#define HD_   64
#define FF_   1024
#define MH_   64      // M_*H_
#define TWOD_ 1024

// ---------------- scratch (device globals; no allocation allowed) ----------------
__device__ float g_q [M_*B_*D_];        // q projection            [M][B][D]
__device__ float g_qk[B_*MH_*D_];       // q folded through Wk     [B][MH][D]
__device__ float g_w [B_*MH_*S_];       // scores -> softmax w     [B][MH][S]
__device__ float g_wv[B_*MH_*D_];       // w @ value_in            [B][MH][D]
__device__ float g_ao[M_*B_*D_];        // attention output (pre-Wo) [M][B][D]
__device__ float g_x [M_*B_*TWOD_];     // relu(concat(attn_out, prev_state)) [M][B][2D]
__device__ float g_h [4*M_*B_*FF_];     // MLP hidden (out heads)  [G*M][B][FF]
__device__ float g_hg[4*M_*B_*FF_];     // MLP hidden (gate heads) [G*M][B][FF]
__device__ float g_o [4*M_*B_*D_];      // tanh output             [G*M][B][D]

// ---------------- generic 64-row x 64-col GEMM tile core ----------------
// C[r,c] = sum_k A[r*lda + k] * (TB ? B[c*ldb + k] : B[k*ldb + c])  (+bias[c], epilogue)
// Requirements (all satisfied by every call site): 64 rows, 64 cols per block,
// K % 16 == 0, all pointers/offsets 16B aligned, lda/ldb/ldc % 4 == 0.
template<bool TB, int EPI>
__device__ __forceinline__ void gemm64(const float* __restrict__ A, int lda,
                                       const float* __restrict__ Bp, int ldb,
                                       float* __restrict__ C, int ldc,
                                       int K, const float* __restrict__ bias)
{
    __shared__ float As[16][64];
    __shared__ float Bs[16][64];
    const int tid = threadIdx.x;             // 256 threads
    const int tx = tid & 15, ty = tid >> 4;  // 16x16 -> 4x4 micro-tiles
    const int ar = tid >> 2;                 // 0..63 (row / NT col)
    const int ak = (tid & 3) << 2;           // 0,4,8,12
    const int nk = tid >> 4;                 // NN loader: k row 0..15
    const int nc = (tid & 15) << 2;          // NN loader: col quad

    float acc[4][4] = {};

    for (int k0 = 0; k0 < K; k0 += 16) {
        __syncthreads();
        float4 av = *(const float4*)(A + ar * lda + k0 + ak);
        As[ak + 0][ar] = av.x; As[ak + 1][ar] = av.y;
        As[ak + 2][ar] = av.z; As[ak + 3][ar] = av.w;
        if (TB) {
            float4 bv = *(const float4*)(Bp + ar * ldb + k0 + ak);
            Bs[ak + 0][ar] = bv.x; Bs[ak + 1][ar] = bv.y;
            Bs[ak + 2][ar] = bv.z; Bs[ak + 3][ar] = bv.w;
        } else {
            *(float4*)&Bs[nk][nc] = *(const float4*)(Bp + (k0 + nk) * ldb + nc);
        }
        __syncthreads();
        #pragma unroll
        for (int kk = 0; kk < 16; kk++) {
            float4 a4 = *(const float4*)&As[kk][ty << 2];
            float4 b4 = *(const float4*)&Bs[kk][tx << 2];
            float aa[4] = {a4.x, a4.y, a4.z, a4.w};
            float bb[4] = {b4.x, b4.y, b4.z, b4.w};
            #pragma unroll
            for (int i = 0; i < 4; i++)
                #pragma unroll
                for (int j = 0; j < 4; j++)
                    acc[i][j] += aa[i] * bb[j];
        }
    }

    #pragma unroll
    for (int i = 0; i < 4; i++) {
        int r = (ty << 2) + i;
        #pragma unroll
        for (int j = 0; j < 4; j++) {
            int c = (tx << 2) + j;
            float v = acc[i][j];
            if (bias) v += bias[c];
            if (EPI >= 1) v = fmaxf(v, 0.0f);
            if (EPI == 2) v = tanhf(v);
            C[r * ldc + c] = v;
        }
    }
}

// ---------------- stage wrappers ----------------

// Stage 1: q[m,b,:] = prev_query[m] @ Wq[m] + bq[m].  grid(D/64, 1, M)
__global__ void __launch_bounds__(256) k_qproj(const float* __restrict__ pq,
                                               const float* __restrict__ Wq,
                                               const float* __restrict__ bq)
{
    int m = blockIdx.z, n0 = blockIdx.x * 64;
    gemm64<false, 0>(pq + m * B_ * D_, D_,
                     Wq + m * D_ * D_ + n0, D_,
                     g_q + m * B_ * D_ + n0, D_,
                     D_, bq + m * D_ + n0);
}

// Stage 2: qk[b, m*H+h, c] = sum_d q[m,b,h*64+d] * Wk[m,c,h*64+d].  grid(D/64, 1, M*H)
__global__ void __launch_bounds__(256) k_qk(const float* __restrict__ Wk)
{
    int m = blockIdx.z >> 3, h = blockIdx.z & 7, n0 = blockIdx.x * 64;
    gemm64<true, 0>(g_q + m * B_ * D_ + h * HD_, D_,
                    Wk + m * D_ * D_ + n0 * D_ + h * HD_, D_,
                    g_qk + (m * H_ + h) * D_ + n0, MH_ * D_,
                    HD_, nullptr);
}

// Stage 3: scores[b, mh, s] = sum_c qk[b,mh,c] * key_in[s,b,c].  grid(S/64, 1, B)
__global__ void __launch_bounds__(256) k_scores(const float* __restrict__ key_in)
{
    int b = blockIdx.z, n0 = blockIdx.x * 64;
    gemm64<true, 0>(g_qk + b * MH_ * D_, D_,
                    key_in + (long)n0 * B_ * D_ + b * D_, B_ * D_,
                    g_w + b * MH_ * S_ + n0, S_,
                    D_, nullptr);
}

// Stage 4: softmax over s with the qh·bk bias folded in.  one warp per (b,mh) row.
__global__ void __launch_bounds__(256) k_softmax(const float* __restrict__ bk)
{
    int row = blockIdx.x * 8 + (threadIdx.x >> 5);   // 0..B*MH-1
    int lane = threadIdx.x & 31;
    int b = row >> 6, mh = row & 63;
    int m = mh >> 3, h = mh & 7;

    const float* qp  = g_q + m * B_ * D_ + b * D_ + h * HD_;
    const float* bkp = bk + m * D_ + h * HD_;
    float bias = qp[lane] * bkp[lane] + qp[lane + 32] * bkp[lane + 32];
    #pragma unroll
    for (int o = 16; o; o >>= 1) bias += __shfl_xor_sync(0xffffffffu, bias, o);

    float* wrow = g_w + b * MH_ * S_ + mh * S_;
    float v[4], mx = -INFINITY;
    #pragma unroll
    for (int i = 0; i < 4; i++) {
        v[i] = (wrow[lane + 32 * i] + bias) * 0.125f;   // 1/sqrt(64)
        mx = fmaxf(mx, v[i]);
    }
    #pragma unroll
    for (int o = 16; o; o >>= 1) mx = fmaxf(mx, __shfl_xor_sync(0xffffffffu, mx, o));
    float sum = 0.0f;
    #pragma unroll
    for (int i = 0; i < 4; i++) { v[i] = __expf(v[i] - mx); sum += v[i]; }
    #pragma unroll
    for (int o = 16; o; o >>= 1) sum += __shfl_xor_sync(0xffffffffu, sum, o);
    float inv = 1.0f / sum;
    #pragma unroll
    for (int i = 0; i < 4; i++) wrow[lane + 32 * i] = v[i] * inv;
}

// Stage 5: wv[b, mh, c] = sum_s w[b,mh,s] * value_in[s,b,c].  grid(D/64, 1, B)
__global__ void __launch_bounds__(256) k_wv(const float* __restrict__ value_in)
{
    int b = blockIdx.z, n0 = blockIdx.x * 64;
    gemm64<false, 0>(g_w + b * MH_ * S_, S_,
                     value_in + b * D_ + n0, B_ * D_,
                     g_wv + b * MH_ * D_ + n0, D_,
                     S_, nullptr);
}

// Stage 6: ao[m,b,h*64+d] = sum_c wv[b,mh,c] * Wv[m,c,h*64+d] + bv.  grid(1, 1, M*H)
__global__ void __launch_bounds__(256) k_ao(const float* __restrict__ Wv,
                                            const float* __restrict__ bv)
{
    int m = blockIdx.z >> 3, h = blockIdx.z & 7;
    gemm64<false, 0>(g_wv + (m * H_ + h) * D_, MH_ * D_,
                     Wv + m * D_ * D_ + h * HD_, D_,
                     g_ao + m * B_ * D_ + h * HD_, D_,
                     D_, bv + m * D_ + h * HD_);
}

// Stage 7: x[:, 0:D] = relu(ao @ Wo + bo).  grid(D/64, 1, M)
__global__ void __launch_bounds__(256) k_attnout(const float* __restrict__ Wo,
                                                 const float* __restrict__ bo)
{
    int m = blockIdx.z, n0 = blockIdx.x * 64;
    gemm64<false, 1>(g_ao + m * B_ * D_, D_,
                     Wo + m * D_ * D_ + n0, D_,
                     g_x + m * B_ * TWOD_ + n0, TWOD_,
                     D_, bo + m * D_ + n0);
}

// Stage 7b: x[:, D:2D] = relu(prev_state)
__global__ void __launch_bounds__(256) k_xfill(const float* __restrict__ ps)
{
    int i = blockIdx.x * 256 + threadIdx.x;
    if (i < M_ * B_ * D_) {
        int mb = i >> 9, d = i & (D_ - 1);
        g_x[mb * TWOD_ + D_ + d] = fmaxf(ps[i], 0.0f);
    }
}

// Stage 8: hidden = relu(x @ W1 + b1)  (which=0 -> g_h with W1, which=1 -> g_hg with Wg1)
// grid(FF/64, 1, 4*M)
__global__ void __launch_bounds__(256) k_mlp1(const float* __restrict__ W,
                                              const float* __restrict__ bvec,
                                              int which)
{
    int gm = blockIdx.z, m = gm & 7, n0 = blockIdx.x * 64;
    float* out = which ? g_hg : g_h;
    gemm64<false, 1>(g_x + m * B_ * TWOD_, TWOD_,
                     W + (long)gm * TWOD_ * FF_ + n0, FF_,
                     out + (long)gm * B_ * FF_ + n0, FF_,
                     TWOD_, bvec + gm * FF_ + n0);
}

// Stage 9: out = tanh(relu(h @ W2 + b2)).  grid(D/64, 1, 4*M)
__global__ void __launch_bounds__(256) k_mlp2(const float* __restrict__ W2,
                                              const float* __restrict__ b2)
{
    int gm = blockIdx.z, n0 = blockIdx.x * 64;
    gemm64<false, 2>(g_h + (long)gm * B_ * FF_, FF_,
                     W2 + (long)gm * FF_ * D_ + n0, D_,
                     g_o + (long)gm * B_ * D_ + n0, D_,
                     FF_, b2 + gm * D_ + n0);
}

// Stage 10: gate = sigmoid(hg . Wg2 + bg2);  out[(g+1)%4] = gate*tanh_out + (1-gate)*prev[g]
// one block (128 thr) per (g, m, b): grid 4*M*B
__global__ void __launch_bounds__(128) k_final(const float* __restrict__ Wg2,
                                               const float* __restrict__ bg2,
                                               const float* __restrict__ pq,
                                               const float* __restrict__ pk,
                                               const float* __restrict__ pv,
                                               const float* __restrict__ ps,
                                               float* __restrict__ out)
{
    int z = blockIdx.x;
    int g = z >> 9, rem = z & 511;      // M*B = 512
    int m = rem >> 6, b = rem & 63;
    int gm = g * M_ + m;
    int tid = threadIdx.x, lane = tid & 31;

    const float* hg = g_hg + ((long)gm * B_ + b) * FF_;
    const float* wg = Wg2 + (long)gm * FF_;
    float s = 0.0f;
    for (int f = tid; f < FF_; f += 128) s += hg[f] * wg[f];
    #pragma unroll
    for (int o = 16; o; o >>= 1) s += __shfl_xor_sync(0xffffffffu, s, o);
    __shared__ float red[4];
    if (lane == 0) red[tid >> 5] = s;
    __syncthreads();
    float tot = red[0] + red[1] + red[2] + red[3];
    float gate = 1.0f / (1.0f + __expf(-(tot + bg2[gm])));

    const float* prevs[4] = {pq, pk, pv, ps};
    const float* pr = prevs[g] + ((long)m * B_ + b) * D_;
    const float* ob = g_o + ((long)gm * B_ + b) * D_;
    float* dst = out + (((long)((g + 1) & 3) * M_ + m) * B_ + b) * D_;
    for (int d = tid; d < D_; d += 128)
        dst[d] = gate * ob[d] + (1.0f - gate) * pr[d];
}

// ---------------- launch ----------------
extern "C" void kernel_launch(void* const* d_in, const int* in_sizes, int n_in,
                              void* d_out, int out_size)
{
    const float* prev_state = (const float*)d_in[0];
    const float* prev_query = (const float*)d_in[1];
    const float* prev_key   = (const float*)d_in[2];
    const float* prev_value = (const float*)d_in[3];
    const float* key_in     = (const float*)d_in[4];
    const float* value_in   = (const float*)d_in[5];
    const float* Wq  = (const float*)d_in[6];
    const float* bq  = (const float*)d_in[7];
    const float* Wk  = (const float*)d_in[8];
    const float* bk  = (const float*)d_in[9];
    const float* Wv  = (const float*)d_in[10];
    const float* bv  = (const float*)d_in[11];
    const float* Wo  = (const float*)d_in[12];
    const float* bo  = (const float*)d_in[13];
    const float* W1  = (const float*)d_in[14];
    const float* b1  = (const float*)d_in[15];
    const float* W2  = (const float*)d_in[16];
    const float* b2  = (const float*)d_in[17];
    const float* Wg1 = (const float*)d_in[18];
    const float* bg1 = (const float*)d_in[19];
    const float* Wg2 = (const float*)d_in[20];
    const float* bg2 = (const float*)d_in[21];
    float* out = (float*)d_out;

    k_qproj  <<<dim3(D_ / 64, 1, M_),     256>>>(prev_query, Wq, bq);
    k_qk     <<<dim3(D_ / 64, 1, M_*H_),  256>>>(Wk);
    k_scores <<<dim3(S_ / 64, 1, B_),     256>>>(key_in);
    k_softmax<<<(B_ * MH_) / 8,           256>>>(bk);
    k_wv     <<<dim3(D_ / 64, 1, B_),     256>>>(value_in);
    k_ao     <<<dim3(1, 1, M_*H_),        256>>>(Wv, bv);
    k_attnout<<<dim3(D_ / 64, 1, M_),     256>>>(Wo, bo);
    k_xfill  <<<(M_*B_*D_ + 255) / 256,   256>>>(prev_state);
    k_mlp1   <<<dim3(FF_ / 64, 1, 4*M_),  256>>>(W1, b1, 0);
    k_mlp1   <<<dim3(FF_ / 64, 1, 4*M_),  256>>>(Wg1, bg1, 1);
    k_mlp2   <<<dim3(D_ / 64, 1, 4*M_),   256>>>(W2, b2);
    k_final  <<<4 * M_ * B_,              128>>>(Wg2, bg2, prev_query, prev_key,
                                                 prev_value, prev_state, out);
}

// round 3
// speedup vs baseline: 1.0005x; 1.0005x over previous
#include <cuda_runtime.h>
#include <math.h>

#define M_    8
#define B_    64
#define S_    128
#define D_    512
#define H_    8
#define HD_   64
#define FF_   1024
#define MH_   64      // M_*H_
#define TWOD_ 1024

// ---------------- scratch (device globals; no allocation allowed) ----------------
__device__ float g_q [M_*B_*D_];        // q projection            [M][B][D]
__device__ float g_qk[B_*MH_*D_];       // q folded through Wk     [B][MH][D]
__device__ float g_w [B_*MH_*S_];       // scores -> softmax w     [B][MH][S]
__device__ float g_wv[B_*MH_*D_];       // w @ value_in            [B][MH][D]
__device__ float g_ao[M_*B_*D_];        // attention output (pre-Wo) [M][B][D]
__device__ float g_x [M_*B_*TWOD_];     // relu(concat(attn_out, prev_state)) [M][B][2D]
__device__ float g_h [4*M_*B_*FF_];     // MLP hidden (out heads)  [G*M][B][FF]
__device__ float g_hg[4*M_*B_*FF_];     // MLP hidden (gate heads) [G*M][B][FF]
__device__ float g_o [4*M_*B_*D_];      // tanh output             [G*M][B][D]

// ---------------- generic 64-row x 64-col GEMM tile core ----------------
// C[r,c] = sum_k A[r*lda + k] * (TB ? B[c*ldb + k] : B[k*ldb + c])  (+bias[c], epilogue)
// Requirements (all satisfied by every call site): 64 rows, 64 cols per block,
// K % 16 == 0, all pointers/offsets 16B aligned, lda/ldb/ldc % 4 == 0.
template<bool TB, int EPI>
__device__ __forceinline__ void gemm64(const float* __restrict__ A, int lda,
                                       const float* __restrict__ Bp, int ldb,
                                       float* __restrict__ C, int ldc,
                                       int K, const float* __restrict__ bias)
{
    __shared__ float As[16][64];
    __shared__ float Bs[16][64];
    const int tid = threadIdx.x;             // 256 threads
    const int tx = tid & 15, ty = tid >> 4;  // 16x16 -> 4x4 micro-tiles
    const int ar = tid >> 2;                 // 0..63 (row / NT col)
    const int ak = (tid & 3) << 2;           // 0,4,8,12
    const int nk = tid >> 4;                 // NN loader: k row 0..15
    const int nc = (tid & 15) << 2;          // NN loader: col quad

    float acc[4][4] = {};

    for (int k0 = 0; k0 < K; k0 += 16) {
        __syncthreads();
        float4 av = *(const float4*)(A + ar * lda + k0 + ak);
        As[ak + 0][ar] = av.x; As[ak + 1][ar] = av.y;
        As[ak + 2][ar] = av.z; As[ak + 3][ar] = av.w;
        if (TB) {
            float4 bv = *(const float4*)(Bp + ar * ldb + k0 + ak);
            Bs[ak + 0][ar] = bv.x; Bs[ak + 1][ar] = bv.y;
            Bs[ak + 2][ar] = bv.z; Bs[ak + 3][ar] = bv.w;
        } else {
            *(float4*)&Bs[nk][nc] = *(const float4*)(Bp + (k0 + nk) * ldb + nc);
        }
        __syncthreads();
        #pragma unroll
        for (int kk = 0; kk < 16; kk++) {
            float4 a4 = *(const float4*)&As[kk][ty << 2];
            float4 b4 = *(const float4*)&Bs[kk][tx << 2];
            float aa[4] = {a4.x, a4.y, a4.z, a4.w};
            float bb[4] = {b4.x, b4.y, b4.z, b4.w};
            #pragma unroll
            for (int i = 0; i < 4; i++)
                #pragma unroll
                for (int j = 0; j < 4; j++)
                    acc[i][j] += aa[i] * bb[j];
        }
    }

    #pragma unroll
    for (int i = 0; i < 4; i++) {
        int r = (ty << 2) + i;
        #pragma unroll
        for (int j = 0; j < 4; j++) {
            int c = (tx << 2) + j;
            float v = acc[i][j];
            if (bias) v += bias[c];
            if (EPI >= 1) v = fmaxf(v, 0.0f);
            if (EPI == 2) v = tanhf(v);
            C[r * ldc + c] = v;
        }
    }
}

// ---------------- stage wrappers ----------------

// Stage 1: q[m,b,:] = prev_query[m] @ Wq[m] + bq[m].  grid(D/64, 1, M)
__global__ void __launch_bounds__(256) k_qproj(const float* __restrict__ pq,
                                               const float* __restrict__ Wq,
                                               const float* __restrict__ bq)
{
    int m = blockIdx.z, n0 = blockIdx.x * 64;
    gemm64<false, 0>(pq + m * B_ * D_, D_,
                     Wq + m * D_ * D_ + n0, D_,
                     g_q + m * B_ * D_ + n0, D_,
                     D_, bq + m * D_ + n0);
}

// Stage 2: qk[b, m*H+h, c] = sum_d q[m,b,h*64+d] * Wk[m,c,h*64+d].  grid(D/64, 1, M*H)
__global__ void __launch_bounds__(256) k_qk(const float* __restrict__ Wk)
{
    int m = blockIdx.z >> 3, h = blockIdx.z & 7, n0 = blockIdx.x * 64;
    gemm64<true, 0>(g_q + m * B_ * D_ + h * HD_, D_,
                    Wk + m * D_ * D_ + n0 * D_ + h * HD_, D_,
                    g_qk + (m * H_ + h) * D_ + n0, MH_ * D_,
                    HD_, nullptr);
}

// Stage 3: scores[b, mh, s] = sum_c qk[b,mh,c] * key_in[s,b,c].  grid(S/64, 1, B)
__global__ void __launch_bounds__(256) k_scores(const float* __restrict__ key_in)
{
    int b = blockIdx.z, n0 = blockIdx.x * 64;
    gemm64<true, 0>(g_qk + b * MH_ * D_, D_,
                    key_in + (long)n0 * B_ * D_ + b * D_, B_ * D_,
                    g_w + b * MH_ * S_ + n0, S_,
                    D_, nullptr);
}

// Stage 4: softmax over s with the qh·bk bias folded in.  one warp per (b,mh) row.
__global__ void __launch_bounds__(256) k_softmax(const float* __restrict__ bk)
{
    int row = blockIdx.x * 8 + (threadIdx.x >> 5);   // 0..B*MH-1
    int lane = threadIdx.x & 31;
    int b = row >> 6, mh = row & 63;
    int m = mh >> 3, h = mh & 7;

    const float* qp  = g_q + m * B_ * D_ + b * D_ + h * HD_;
    const float* bkp = bk + m * D_ + h * HD_;
    float bias = qp[lane] * bkp[lane] + qp[lane + 32] * bkp[lane + 32];
    #pragma unroll
    for (int o = 16; o; o >>= 1) bias += __shfl_xor_sync(0xffffffffu, bias, o);

    float* wrow = g_w + b * MH_ * S_ + mh * S_;
    float v[4], mx = -INFINITY;
    #pragma unroll
    for (int i = 0; i < 4; i++) {
        v[i] = (wrow[lane + 32 * i] + bias) * 0.125f;   // 1/sqrt(64)
        mx = fmaxf(mx, v[i]);
    }
    #pragma unroll
    for (int o = 16; o; o >>= 1) mx = fmaxf(mx, __shfl_xor_sync(0xffffffffu, mx, o));
    float sum = 0.0f;
    #pragma unroll
    for (int i = 0; i < 4; i++) { v[i] = __expf(v[i] - mx); sum += v[i]; }
    #pragma unroll
    for (int o = 16; o; o >>= 1) sum += __shfl_xor_sync(0xffffffffu, sum, o);
    float inv = 1.0f / sum;
    #pragma unroll
    for (int i = 0; i < 4; i++) wrow[lane + 32 * i] = v[i] * inv;
}

// Stage 5: wv[b, mh, c] = sum_s w[b,mh,s] * value_in[s,b,c].  grid(D/64, 1, B)
__global__ void __launch_bounds__(256) k_wv(const float* __restrict__ value_in)
{
    int b = blockIdx.z, n0 = blockIdx.x * 64;
    gemm64<false, 0>(g_w + b * MH_ * S_, S_,
                     value_in + b * D_ + n0, B_ * D_,
                     g_wv + b * MH_ * D_ + n0, D_,
                     S_, nullptr);
}

// Stage 6: ao[m,b,h*64+d] = sum_c wv[b,mh,c] * Wv[m,c,h*64+d] + bv.  grid(1, 1, M*H)
__global__ void __launch_bounds__(256) k_ao(const float* __restrict__ Wv,
                                            const float* __restrict__ bv)
{
    int m = blockIdx.z >> 3, h = blockIdx.z & 7;
    gemm64<false, 0>(g_wv + (m * H_ + h) * D_, MH_ * D_,
                     Wv + m * D_ * D_ + h * HD_, D_,
                     g_ao + m * B_ * D_ + h * HD_, D_,
                     D_, bv + m * D_ + h * HD_);
}

// Stage 7: x[:, 0:D] = relu(ao @ Wo + bo).  grid(D/64, 1, M)
__global__ void __launch_bounds__(256) k_attnout(const float* __restrict__ Wo,
                                                 const float* __restrict__ bo)
{
    int m = blockIdx.z, n0 = blockIdx.x * 64;
    gemm64<false, 1>(g_ao + m * B_ * D_, D_,
                     Wo + m * D_ * D_ + n0, D_,
                     g_x + m * B_ * TWOD_ + n0, TWOD_,
                     D_, bo + m * D_ + n0);
}

// Stage 7b: x[:, D:2D] = relu(prev_state)
__global__ void __launch_bounds__(256) k_xfill(const float* __restrict__ ps)
{
    int i = blockIdx.x * 256 + threadIdx.x;
    if (i < M_ * B_ * D_) {
        int mb = i >> 9, d = i & (D_ - 1);
        g_x[mb * TWOD_ + D_ + d] = fmaxf(ps[i], 0.0f);
    }
}

// Stage 8: hidden = relu(x @ W1 + b1)  (which=0 -> g_h with W1, which=1 -> g_hg with Wg1)
// grid(FF/64, 1, 4*M)
__global__ void __launch_bounds__(256) k_mlp1(const float* __restrict__ W,
                                              const float* __restrict__ bvec,
                                              int which)
{
    int gm = blockIdx.z, m = gm & 7, n0 = blockIdx.x * 64;
    float* out = which ? g_hg : g_h;
    gemm64<false, 1>(g_x + m * B_ * TWOD_, TWOD_,
                     W + (long)gm * TWOD_ * FF_ + n0, FF_,
                     out + (long)gm * B_ * FF_ + n0, FF_,
                     TWOD_, bvec + gm * FF_ + n0);
}

// Stage 9: out = tanh(relu(h @ W2 + b2)).  grid(D/64, 1, 4*M)
__global__ void __launch_bounds__(256) k_mlp2(const float* __restrict__ W2,
                                              const float* __restrict__ b2)
{
    int gm = blockIdx.z, n0 = blockIdx.x * 64;
    gemm64<false, 2>(g_h + (long)gm * B_ * FF_, FF_,
                     W2 + (long)gm * FF_ * D_ + n0, D_,
                     g_o + (long)gm * B_ * D_ + n0, D_,
                     FF_, b2 + gm * D_ + n0);
}

// Stage 10: gate = sigmoid(hg . Wg2 + bg2);  out[(g+1)%4] = gate*tanh_out + (1-gate)*prev[g]
// one block (128 thr) per (g, m, b): grid 4*M*B
__global__ void __launch_bounds__(128) k_final(const float* __restrict__ Wg2,
                                               const float* __restrict__ bg2,
                                               const float* __restrict__ pq,
                                               const float* __restrict__ pk,
                                               const float* __restrict__ pv,
                                               const float* __restrict__ ps,
                                               float* __restrict__ out)
{
    int z = blockIdx.x;
    int g = z >> 9, rem = z & 511;      // M*B = 512
    int m = rem >> 6, b = rem & 63;
    int gm = g * M_ + m;
    int tid = threadIdx.x, lane = tid & 31;

    const float* hg = g_hg + ((long)gm * B_ + b) * FF_;
    const float* wg = Wg2 + (long)gm * FF_;
    float s = 0.0f;
    for (int f = tid; f < FF_; f += 128) s += hg[f] * wg[f];
    #pragma unroll
    for (int o = 16; o; o >>= 1) s += __shfl_xor_sync(0xffffffffu, s, o);
    __shared__ float red[4];
    if (lane == 0) red[tid >> 5] = s;
    __syncthreads();
    float tot = red[0] + red[1] + red[2] + red[3];
    float gate = 1.0f / (1.0f + __expf(-(tot + bg2[gm])));

    const float* prevs[4] = {pq, pk, pv, ps};
    const float* pr = prevs[g] + ((long)m * B_ + b) * D_;
    const float* ob = g_o + ((long)gm * B_ + b) * D_;
    float* dst = out + (((long)((g + 1) & 3) * M_ + m) * B_ + b) * D_;
    for (int d = tid; d < D_; d += 128)
        dst[d] = gate * ob[d] + (1.0f - gate) * pr[d];
}

// ---------------- launch ----------------
extern "C" void kernel_launch(void* const* d_in, const int* in_sizes, int n_in,
                              void* d_out, int out_size)
{
    const float* prev_state = (const float*)d_in[0];
    const float* prev_query = (const float*)d_in[1];
    const float* prev_key   = (const float*)d_in[2];
    const float* prev_value = (const float*)d_in[3];
    const float* key_in     = (const float*)d_in[4];
    const float* value_in   = (const float*)d_in[5];
    const float* Wq  = (const float*)d_in[6];
    const float* bq  = (const float*)d_in[7];
    const float* Wk  = (const float*)d_in[8];
    const float* bk  = (const float*)d_in[9];
    const float* Wv  = (const float*)d_in[10];
    const float* bv  = (const float*)d_in[11];
    const float* Wo  = (const float*)d_in[12];
    const float* bo  = (const float*)d_in[13];
    const float* W1  = (const float*)d_in[14];
    const float* b1  = (const float*)d_in[15];
    const float* W2  = (const float*)d_in[16];
    const float* b2  = (const float*)d_in[17];
    const float* Wg1 = (const float*)d_in[18];
    const float* bg1 = (const float*)d_in[19];
    const float* Wg2 = (const float*)d_in[20];
    const float* bg2 = (const float*)d_in[21];
    float* out = (float*)d_out;

    k_qproj  <<<dim3(D_ / 64, 1, M_),     256>>>(prev_query, Wq, bq);
    k_qk     <<<dim3(D_ / 64, 1, M_*H_),  256>>>(Wk);
    k_scores <<<dim3(S_ / 64, 1, B_),     256>>>(key_in);
    k_softmax<<<(B_ * MH_) / 8,           256>>>(bk);
    k_wv     <<<dim3(D_ / 64, 1, B_),     256>>>(value_in);
    k_ao     <<<dim3(1, 1, M_*H_),        256>>>(Wv, bv);
    k_attnout<<<dim3(D_ / 64, 1, M_),     256>>>(Wo, bo);
    k_xfill  <<<(M_*B_*D_ + 255) / 256,   256>>>(prev_state);
    k_mlp1   <<<dim3(FF_ / 64, 1, 4*M_),  256>>>(W1, b1, 0);
    k_mlp1   <<<dim3(FF_ / 64, 1, 4*M_),  256>>>(Wg1, bg1, 1);
    k_mlp2   <<<dim3(D_ / 64, 1, 4*M_),   256>>>(W2, b2);
    k_final  <<<4 * M_ * B_,              128>>>(Wg2, bg2, prev_query, prev_key,
                                                 prev_value, prev_state, out);
}

// round 6
// speedup vs baseline: 1.0282x; 1.0277x over previous
#include <cuda_runtime.h>
#include <math.h>
#include <stdint.h>

#define M_    8
#define B_    64
#define S_    128
#define D_    512
#define H_    8
#define HD_   64
#define FF_   1024
#define MH_   64
#define TWOD_ 1024

// ---------------- scratch ----------------
__device__ float g_q [M_*B_*D_];
__device__ float g_qk[B_*MH_*D_];
__device__ float g_w [B_*MH_*S_];
__device__ float g_wv[B_*MH_*D_];
__device__ float g_ao[M_*B_*D_];
__device__ float g_x [M_*B_*TWOD_];
__device__ float g_h [4*M_*B_*FF_];
__device__ float g_hg[4*M_*B_*FF_];
__device__ float g_o [4*M_*B_*D_];

__device__ __forceinline__ uint32_t f2tf(float f) {
    uint32_t u; asm("cvt.rna.tf32.f32 %0, %1;" : "=r"(u) : "f"(f)); return u;
}

__device__ __forceinline__ void mma_tf32(float* d, const uint32_t* a, const uint32_t* b) {
    asm volatile("mma.sync.aligned.m16n8k8.row.col.f32.tf32.tf32.f32 "
                 "{%0,%1,%2,%3}, {%4,%5,%6,%7}, {%8,%9}, {%0,%1,%2,%3};"
                 : "+f"(d[0]), "+f"(d[1]), "+f"(d[2]), "+f"(d[3])
                 : "r"(a[0]), "r"(a[1]), "r"(a[2]), "r"(a[3]), "r"(b[0]), "r"(b[1]));
}

// ============ tensor-pipe tf32 GEMM: C[b][n] = epi(sum_k X[b][k]*W[k][n] + bias[n]) ============
// CTA tile: 128 features (mma M) x 64 batch (mma N). 8 warps = 4(feat) x 2(batch) of 32x32.
// Smem: Ws[128][36] = W^T tile (feature-major, k contiguous), Xs[64][36]. Stride 36 ->
// conflict-free fragment loads, 16B-aligned v4 stores.
#define WSTRIDE 36

// xsel: 0=Xext 1=g_x 2=g_ao 3=g_h ; csel: 0=g_q 1=g_x 2=g_h 3=g_hg 4=g_o
template<int EPI>
__global__ void __launch_bounds__(256)
k_tgemm(const float* __restrict__ W, int ldw, long long wz,
        const float* __restrict__ Xext, int xsel, int ldx, long long xz, int xmask,
        int csel, int ldc, long long cz,
        const float* __restrict__ bias, int bz, int K)
{
    __shared__ float Ws[128 * WSTRIDE];
    __shared__ float Xs[64 * WSTRIDE];

    const float* Xbase = (xsel == 0) ? Xext : (xsel == 1) ? g_x : (xsel == 2) ? g_ao : g_h;
    float* Cbase = (csel == 0) ? g_q : (csel == 1) ? g_x : (csel == 2) ? g_h
                 : (csel == 3) ? g_hg : g_o;

    const int z = blockIdx.z;
    W    += (long long)z * wz + blockIdx.x * 128;
    const float* X = Xbase + (long long)(z & xmask) * xz;
    float* C = Cbase + (long long)z * cz + blockIdx.x * 128;
    bias += (long long)z * bz + blockIdx.x * 128;

    const int tid  = threadIdx.x;
    const int lane = tid & 31;
    const int warp = tid >> 5;
    const int wn   = warp & 3;          // feature group: n0w = wn*32
    const int wb   = warp >> 2;         // batch group:   b0w = wb*32
    const int n0w  = wn * 32;
    const int b0w  = wb * 32;
    const int gid  = lane >> 2;         // 0..7
    const int t4   = lane & 3;          // 0..3

    const int nl  = tid & 127;          // W loader feature column
    const int kq0 = tid >> 7;           // 0/1

    float acc[2][4][4] = {};

    const int nchunk = K >> 5;
    for (int c = 0; c < nchunk; c++) {
        const int k0 = c << 5;
        if (c) __syncthreads();
        // --- W^T tile: Ws[n][k] = tf32(W[k0+k][n]) ---
        #pragma unroll
        for (int it = 0; it < 4; it++) {
            int kq = kq0 + it * 2;                  // 0..7
            const float* wp = W + (long long)(k0 + kq * 4) * ldw + nl;
            uint32_t v0 = f2tf(wp[0]),       v1 = f2tf(wp[ldw]);
            uint32_t v2 = f2tf(wp[2 * ldw]), v3 = f2tf(wp[3 * ldw]);
            float4* dst = (float4*)&Ws[nl * WSTRIDE + kq * 4];
            *dst = make_float4(__uint_as_float(v0), __uint_as_float(v1),
                               __uint_as_float(v2), __uint_as_float(v3));
        }
        // --- X tile: Xs[b][k] = tf32(X[b][k0+k]) ---
        #pragma unroll
        for (int it = 0; it < 2; it++) {
            int idx = tid + it * 256;
            int b = idx >> 3, kq = idx & 7;
            float4 xv = *(const float4*)(X + (long long)b * ldx + k0 + kq * 4);
            uint32_t v0 = f2tf(xv.x), v1 = f2tf(xv.y), v2 = f2tf(xv.z), v3 = f2tf(xv.w);
            float4* dst = (float4*)&Xs[b * WSTRIDE + kq * 4];
            *dst = make_float4(__uint_as_float(v0), __uint_as_float(v1),
                               __uint_as_float(v2), __uint_as_float(v3));
        }
        __syncthreads();

        #pragma unroll
        for (int ks = 0; ks < 4; ks++) {
            const int kb = ks * 8;
            uint32_t a[2][4], b[4][2];
            #pragma unroll
            for (int mt = 0; mt < 2; mt++) {
                const float* ap = &Ws[(n0w + mt * 16 + gid) * WSTRIDE + kb + t4];
                a[mt][0] = __float_as_uint(ap[0]);
                a[mt][1] = __float_as_uint(ap[8 * WSTRIDE]);
                a[mt][2] = __float_as_uint(ap[4]);
                a[mt][3] = __float_as_uint(ap[8 * WSTRIDE + 4]);
            }
            #pragma unroll
            for (int nt = 0; nt < 4; nt++) {
                const float* bp = &Xs[(b0w + nt * 8 + gid) * WSTRIDE + kb + t4];
                b[nt][0] = __float_as_uint(bp[0]);
                b[nt][1] = __float_as_uint(bp[4]);
            }
            #pragma unroll
            for (int mt = 0; mt < 2; mt++)
                #pragma unroll
                for (int nt = 0; nt < 4; nt++)
                    mma_tf32(acc[mt][nt], a[mt], b[nt]);
        }
    }

    // --- epilogue: acc[mt][nt] c0..c3 -> C[b][n], +bias, EPI ---
    #pragma unroll
    for (int mt = 0; mt < 2; mt++) {
        const int n = n0w + mt * 16 + gid;
        const float bv0 = bias[n], bv1 = bias[n + 8];
        #pragma unroll
        for (int nt = 0; nt < 4; nt++) {
            const int b = b0w + nt * 8 + 2 * t4;
            float v[4] = {acc[mt][nt][0] + bv0, acc[mt][nt][1] + bv0,
                          acc[mt][nt][2] + bv1, acc[mt][nt][3] + bv1};
            #pragma unroll
            for (int j = 0; j < 4; j++) {
                if (EPI >= 1) v[j] = fmaxf(v[j], 0.0f);
                if (EPI == 2) v[j] = tanhf(v[j]);
            }
            C[(long long)b * ldc + n]           = v[0];
            C[(long long)(b + 1) * ldc + n]     = v[1];
            C[(long long)b * ldc + n + 8]       = v[2];
            C[(long long)(b + 1) * ldc + n + 8] = v[3];
        }
    }
}

// ---------------- SIMT 64x64 GEMM core (attention odd shapes) ----------------
template<bool TB, int EPI>
__device__ __forceinline__ void gemm64(const float* __restrict__ A, int lda,
                                       const float* __restrict__ Bp, int ldb,
                                       float* __restrict__ C, int ldc,
                                       int K, const float* __restrict__ bias)
{
    __shared__ float As[16][64];
    __shared__ float Bs[16][64];
    const int tid = threadIdx.x;
    const int tx = tid & 15, ty = tid >> 4;
    const int ar = tid >> 2, ak = (tid & 3) << 2;
    const int nk = tid >> 4, nc = (tid & 15) << 2;
    float acc[4][4] = {};
    for (int k0 = 0; k0 < K; k0 += 16) {
        __syncthreads();
        float4 av = *(const float4*)(A + ar * lda + k0 + ak);
        As[ak + 0][ar] = av.x; As[ak + 1][ar] = av.y;
        As[ak + 2][ar] = av.z; As[ak + 3][ar] = av.w;
        if (TB) {
            float4 bv = *(const float4*)(Bp + ar * ldb + k0 + ak);
            Bs[ak + 0][ar] = bv.x; Bs[ak + 1][ar] = bv.y;
            Bs[ak + 2][ar] = bv.z; Bs[ak + 3][ar] = bv.w;
        } else {
            *(float4*)&Bs[nk][nc] = *(const float4*)(Bp + (k0 + nk) * ldb + nc);
        }
        __syncthreads();
        #pragma unroll
        for (int kk = 0; kk < 16; kk++) {
            float4 a4 = *(const float4*)&As[kk][ty << 2];
            float4 b4 = *(const float4*)&Bs[kk][tx << 2];
            float aa[4] = {a4.x, a4.y, a4.z, a4.w};
            float bb[4] = {b4.x, b4.y, b4.z, b4.w};
            #pragma unroll
            for (int i = 0; i < 4; i++)
                #pragma unroll
                for (int j = 0; j < 4; j++)
                    acc[i][j] += aa[i] * bb[j];
        }
    }
    #pragma unroll
    for (int i = 0; i < 4; i++) {
        int r = (ty << 2) + i;
        #pragma unroll
        for (int j = 0; j < 4; j++) {
            int c = (tx << 2) + j;
            float v = acc[i][j];
            if (bias) v += bias[c];
            if (EPI >= 1) v = fmaxf(v, 0.0f);
            C[r * ldc + c] = v;
        }
    }
}

__global__ void __launch_bounds__(256) k_qk(const float* __restrict__ Wk)
{
    int m = blockIdx.z >> 3, h = blockIdx.z & 7, n0 = blockIdx.x * 64;
    gemm64<true, 0>(g_q + m * B_ * D_ + h * HD_, D_,
                    Wk + m * D_ * D_ + n0 * D_ + h * HD_, D_,
                    g_qk + (m * H_ + h) * D_ + n0, MH_ * D_, HD_, nullptr);
}

__global__ void __launch_bounds__(256) k_scores(const float* __restrict__ key_in)
{
    int b = blockIdx.z, n0 = blockIdx.x * 64;
    gemm64<true, 0>(g_qk + b * MH_ * D_, D_,
                    key_in + (long)n0 * B_ * D_ + b * D_, B_ * D_,
                    g_w + b * MH_ * S_ + n0, S_, D_, nullptr);
}

__global__ void __launch_bounds__(256) k_softmax(const float* __restrict__ bk)
{
    int row = blockIdx.x * 8 + (threadIdx.x >> 5);
    int lane = threadIdx.x & 31;
    int b = row >> 6, mh = row & 63;
    int m = mh >> 3, h = mh & 7;
    const float* qp  = g_q + m * B_ * D_ + b * D_ + h * HD_;
    const float* bkp = bk + m * D_ + h * HD_;
    float bias = qp[lane] * bkp[lane] + qp[lane + 32] * bkp[lane + 32];
    #pragma unroll
    for (int o = 16; o; o >>= 1) bias += __shfl_xor_sync(0xffffffffu, bias, o);
    float* wrow = g_w + b * MH_ * S_ + mh * S_;
    float v[4], mx = -INFINITY;
    #pragma unroll
    for (int i = 0; i < 4; i++) {
        v[i] = (wrow[lane + 32 * i] + bias) * 0.125f;
        mx = fmaxf(mx, v[i]);
    }
    #pragma unroll
    for (int o = 16; o; o >>= 1) mx = fmaxf(mx, __shfl_xor_sync(0xffffffffu, mx, o));
    float sum = 0.0f;
    #pragma unroll
    for (int i = 0; i < 4; i++) { v[i] = __expf(v[i] - mx); sum += v[i]; }
    #pragma unroll
    for (int o = 16; o; o >>= 1) sum += __shfl_xor_sync(0xffffffffu, sum, o);
    float inv = 1.0f / sum;
    #pragma unroll
    for (int i = 0; i < 4; i++) wrow[lane + 32 * i] = v[i] * inv;
}

__global__ void __launch_bounds__(256) k_wv(const float* __restrict__ value_in)
{
    int b = blockIdx.z, n0 = blockIdx.x * 64;
    gemm64<false, 0>(g_w + b * MH_ * S_, S_,
                     value_in + b * D_ + n0, B_ * D_,
                     g_wv + b * MH_ * D_ + n0, D_, S_, nullptr);
}

__global__ void __launch_bounds__(256) k_ao(const float* __restrict__ Wv,
                                            const float* __restrict__ bv)
{
    int m = blockIdx.z >> 3, h = blockIdx.z & 7;
    gemm64<false, 0>(g_wv + (m * H_ + h) * D_, MH_ * D_,
                     Wv + m * D_ * D_ + h * HD_, D_,
                     g_ao + m * B_ * D_ + h * HD_, D_, D_, bv + m * D_ + h * HD_);
}

__global__ void __launch_bounds__(256) k_xfill(const float* __restrict__ ps)
{
    int i = blockIdx.x * 256 + threadIdx.x;
    if (i < M_ * B_ * D_) {
        int mb = i >> 9, d = i & (D_ - 1);
        g_x[mb * TWOD_ + D_ + d] = fmaxf(ps[i], 0.0f);
    }
}

__global__ void __launch_bounds__(128) k_final(const float* __restrict__ Wg2,
                                               const float* __restrict__ bg2,
                                               const float* __restrict__ pq,
                                               const float* __restrict__ pk,
                                               const float* __restrict__ pv,
                                               const float* __restrict__ ps,
                                               float* __restrict__ out)
{
    int z = blockIdx.x;
    int g = z >> 9, rem = z & 511;
    int m = rem >> 6, b = rem & 63;
    int gm = g * M_ + m;
    int tid = threadIdx.x, lane = tid & 31;
    const float* hg = g_hg + ((long)gm * B_ + b) * FF_;
    const float* wg = Wg2 + (long)gm * FF_;
    float s = 0.0f;
    for (int f = tid; f < FF_; f += 128) s += hg[f] * wg[f];
    #pragma unroll
    for (int o = 16; o; o >>= 1) s += __shfl_xor_sync(0xffffffffu, s, o);
    __shared__ float red[4];
    if (lane == 0) red[tid >> 5] = s;
    __syncthreads();
    float tot = red[0] + red[1] + red[2] + red[3];
    float gate = 1.0f / (1.0f + __expf(-(tot + bg2[gm])));
    const float* prevs[4] = {pq, pk, pv, ps};
    const float* pr = prevs[g] + ((long)m * B_ + b) * D_;
    const float* ob = g_o + ((long)gm * B_ + b) * D_;
    float* dst = out + (((long)((g + 1) & 3) * M_ + m) * B_ + b) * D_;
    for (int d = tid; d < D_; d += 128)
        dst[d] = gate * ob[d] + (1.0f - gate) * pr[d];
}

// ---------------- launch ----------------
extern "C" void kernel_launch(void* const* d_in, const int* in_sizes, int n_in,
                              void* d_out, int out_size)
{
    const float* prev_state = (const float*)d_in[0];
    const float* prev_query = (const float*)d_in[1];
    const float* prev_key   = (const float*)d_in[2];
    const float* prev_value = (const float*)d_in[3];
    const float* key_in     = (const float*)d_in[4];
    const float* value_in   = (const float*)d_in[5];
    const float* Wq  = (const float*)d_in[6];
    const float* bq  = (const float*)d_in[7];
    const float* Wk  = (const float*)d_in[8];
    const float* bk  = (const float*)d_in[9];
    const float* Wv  = (const float*)d_in[10];
    const float* bv  = (const float*)d_in[11];
    const float* Wo  = (const float*)d_in[12];
    const float* bo  = (const float*)d_in[13];
    const float* W1  = (const float*)d_in[14];
    const float* b1  = (const float*)d_in[15];
    const float* W2  = (const float*)d_in[16];
    const float* b2  = (const float*)d_in[17];
    const float* Wg1 = (const float*)d_in[18];
    const float* bg1 = (const float*)d_in[19];
    const float* Wg2 = (const float*)d_in[20];
    const float* bg2 = (const float*)d_in[21];
    float* out = (float*)d_out;

    // q = prev_query @ Wq + bq  (tensor)
    k_tgemm<0><<<dim3(4, 1, M_), 256>>>(Wq, D_, (long long)D_ * D_,
                                        prev_query, 0, D_, (long long)B_ * D_, -1,
                                        0, D_, (long long)B_ * D_, bq, D_, D_);
    k_qk     <<<dim3(D_ / 64, 1, M_ * H_), 256>>>(Wk);
    k_scores <<<dim3(S_ / 64, 1, B_),      256>>>(key_in);
    k_softmax<<<(B_ * MH_) / 8,            256>>>(bk);
    k_wv     <<<dim3(D_ / 64, 1, B_),      256>>>(value_in);
    k_ao     <<<dim3(1, 1, M_ * H_),       256>>>(Wv, bv);
    // x[:,0:D] = relu(ao @ Wo + bo)  (tensor)
    k_tgemm<1><<<dim3(4, 1, M_), 256>>>(Wo, D_, (long long)D_ * D_,
                                        nullptr, 2, D_, (long long)B_ * D_, -1,
                                        1, TWOD_, (long long)B_ * TWOD_, bo, D_, D_);
    k_xfill  <<<(M_ * B_ * D_ + 255) / 256, 256>>>(prev_state);
    // h = relu(x @ W1 + b1), hg = relu(x @ Wg1 + bg1)  (tensor)
    k_tgemm<1><<<dim3(8, 1, 32), 256>>>(W1, FF_, (long long)TWOD_ * FF_,
                                        nullptr, 1, TWOD_, (long long)B_ * TWOD_, 7,
                                        2, FF_, (long long)B_ * FF_, b1, FF_, TWOD_);
    k_tgemm<1><<<dim3(8, 1, 32), 256>>>(Wg1, FF_, (long long)TWOD_ * FF_,
                                        nullptr, 1, TWOD_, (long long)B_ * TWOD_, 7,
                                        3, FF_, (long long)B_ * FF_, bg1, FF_, TWOD_);
    // o = tanh(relu(h @ W2 + b2))  (tensor)
    k_tgemm<2><<<dim3(4, 1, 32), 256>>>(W2, D_, (long long)FF_ * D_,
                                        nullptr, 3, FF_, (long long)B_ * FF_, -1,
                                        4, D_, (long long)B_ * D_, b2, D_, FF_);
    k_final  <<<4 * M_ * B_, 128>>>(Wg2, bg2, prev_query, prev_key,
                                    prev_value, prev_state, out);
}

// round 7
// speedup vs baseline: 1.0540x; 1.0251x over previous
#include <cuda_runtime.h>
#include <math.h>
#include <stdint.h>

#define M_    8
#define B_    64
#define S_    128
#define D_    512
#define H_    8
#define HD_   64
#define FF_   1024
#define MH_   64
#define TWOD_ 1024

typedef unsigned long long u64;

// ---------------- scratch ----------------
__device__ float g_q [M_*B_*D_];
__device__ float g_qk[B_*MH_*D_];
__device__ float g_w [B_*MH_*S_];
__device__ float g_wv[B_*MH_*D_];
__device__ float g_ao[M_*B_*D_];
__device__ float g_x [M_*B_*TWOD_];
__device__ float g_h [4*M_*B_*FF_];
__device__ float g_hg[4*M_*B_*FF_];
__device__ float g_o [4*M_*B_*D_];

// ---------------- packed f32x2 helpers ----------------
__device__ __forceinline__ u64 pk2(float x, float y) {
    u64 r; asm("mov.b64 %0, {%1,%2};" : "=l"(r) : "f"(x), "f"(y)); return r;
}
__device__ __forceinline__ void upk2(float& x, float& y, u64 p) {
    asm("mov.b64 {%0,%1}, %2;" : "=f"(x), "=f"(y) : "l"(p));
}
__device__ __forceinline__ void ffma2(u64& d, u64 a, u64 b) {
    asm("fma.rn.f32x2 %0, %1, %2, %0;" : "+l"(d) : "l"(a), "l"(b));
}

// ============ packed-FFMA2 GEMM: C[b][n] = epi(sum_k X[b][k]*W[k][n] + bias[n]) ============
// CTA: 64 batch x NF features. 256 thr: warps 2(b) x 4(f); thread micro 8b x (NF/32)f.
// acc packed over batch pairs (batch-adjacent smem -> natural f32x2 pairs for A).
// xsel: 1=g_x 3=g_h ; csel: 2=g_h 3=g_hg 4=g_o
template<int NF, int EPI>
__global__ void __launch_bounds__(256) k_pgemm(
    const float* __restrict__ Wp, int ldw, long long wz,
    int xsel, int ldx, long long xz, int xmask,
    int csel, int ldc, long long cz,
    const float* __restrict__ bias, int bz, int K)
{
    constexpr int F = NF / 32;              // per-thread feature width (4 or 8)
    __shared__ float As[16][68];            // [k][batch], padded
    __shared__ float Bs[16][NF];            // [k][feature]

    const float* Xbase = (xsel == 1) ? g_x : g_h;
    float* Cbase = (csel == 2) ? g_h : (csel == 3) ? g_hg : g_o;

    const int z = blockIdx.z;
    const float* W = Wp + (long long)z * wz + blockIdx.x * NF;
    const float* X = Xbase + (long long)(z & xmask) * xz;
    float* C = Cbase + (long long)z * cz + blockIdx.x * NF;
    const float* bi = bias + (long long)z * bz + blockIdx.x * NF;

    const int tid = threadIdx.x, lane = tid & 31, warp = tid >> 5;
    const int wb = warp >> 2, wf = warp & 3;
    const int tb = lane & 3,  tf = lane >> 2;
    const int b8 = wb * 32 + tb * 8;            // batch base (8 rows)
    const int f0 = wf * (NF / 4) + tf * F;      // feature base (F cols)

    const int la_b = tid >> 2;                  // A loader: batch row
    const int la_k = (tid & 3) << 2;            // A loader: k quad

    u64 acc[4][F];
    #pragma unroll
    for (int i = 0; i < 4; i++)
        #pragma unroll
        for (int j = 0; j < F; j++) acc[i][j] = 0ull;   // (0.0f, 0.0f)

    for (int k0 = 0; k0 < K; k0 += 16) {
        if (k0) __syncthreads();
        // A: As[k][b] = X[b][k0+k] (transpose)
        {
            float4 xa = *(const float4*)(X + (long long)la_b * ldx + k0 + la_k);
            As[la_k + 0][la_b] = xa.x; As[la_k + 1][la_b] = xa.y;
            As[la_k + 2][la_b] = xa.z; As[la_k + 3][la_b] = xa.w;
        }
        // B: Bs[k][n] = W[k0+k][n] (direct, coalesced)
        #pragma unroll
        for (int j = 0; j < NF / 64; j++) {
            int fidx = tid + j * 256;
            int r = fidx / (NF / 4), c4 = fidx % (NF / 4);
            *(float4*)&Bs[r][c4 * 4] =
                *(const float4*)(W + (long long)(k0 + r) * ldw + c4 * 4);
        }
        __syncthreads();

        #pragma unroll
        for (int kk = 0; kk < 16; kk++) {
            float4 a0 = *(const float4*)&As[kk][b8];
            float4 a1 = *(const float4*)&As[kk][b8 + 4];
            u64 ap[4];
            ap[0] = pk2(a0.x, a0.y); ap[1] = pk2(a0.z, a0.w);
            ap[2] = pk2(a1.x, a1.y); ap[3] = pk2(a1.z, a1.w);

            u64 bd[F];
            {
                float4 bv0 = *(const float4*)&Bs[kk][f0];
                bd[0] = pk2(bv0.x, bv0.x); bd[1] = pk2(bv0.y, bv0.y);
                bd[2] = pk2(bv0.z, bv0.z); bd[3] = pk2(bv0.w, bv0.w);
                if (F == 8) {
                    float4 bv1 = *(const float4*)&Bs[kk][f0 + 4];
                    bd[4] = pk2(bv1.x, bv1.x); bd[5] = pk2(bv1.y, bv1.y);
                    bd[6] = pk2(bv1.z, bv1.z); bd[7] = pk2(bv1.w, bv1.w);
                }
            }
            #pragma unroll
            for (int i = 0; i < 4; i++)
                #pragma unroll
                for (int j = 0; j < F; j++)
                    ffma2(acc[i][j], ap[i], bd[j]);
        }
    }

    // epilogue: acc[i][j] = (C[b8+2i][f0+j], C[b8+2i+1][f0+j])
    #pragma unroll
    for (int i = 0; i < 4; i++) {
        float vlo[F], vhi[F];
        #pragma unroll
        for (int j = 0; j < F; j++) {
            float lo, hi; upk2(lo, hi, acc[i][j]);
            float bb = bi[f0 + j];
            lo += bb; hi += bb;
            if (EPI >= 1) { lo = fmaxf(lo, 0.0f); hi = fmaxf(hi, 0.0f); }
            if (EPI == 2) { lo = tanhf(lo); hi = tanhf(hi); }
            vlo[j] = lo; vhi[j] = hi;
        }
        float* r0 = C + (long long)(b8 + 2 * i) * ldc + f0;
        float* r1 = r0 + ldc;
        #pragma unroll
        for (int j4 = 0; j4 < F; j4 += 4) {
            *(float4*)(r0 + j4) = make_float4(vlo[j4], vlo[j4+1], vlo[j4+2], vlo[j4+3]);
            *(float4*)(r1 + j4) = make_float4(vhi[j4], vhi[j4+1], vhi[j4+2], vhi[j4+3]);
        }
    }
}

// ---------------- SIMT 64x64 GEMM core (attention + small projections) ----------------
template<bool TB, int EPI>
__device__ __forceinline__ void gemm64(const float* __restrict__ A, int lda,
                                       const float* __restrict__ Bp, int ldb,
                                       float* __restrict__ C, int ldc,
                                       int K, const float* __restrict__ bias)
{
    __shared__ float As[16][64];
    __shared__ float Bs[16][64];
    const int tid = threadIdx.x;
    const int tx = tid & 15, ty = tid >> 4;
    const int ar = tid >> 2, ak = (tid & 3) << 2;
    const int nk = tid >> 4, nc = (tid & 15) << 2;
    float acc[4][4] = {};
    for (int k0 = 0; k0 < K; k0 += 16) {
        __syncthreads();
        float4 av = *(const float4*)(A + ar * lda + k0 + ak);
        As[ak + 0][ar] = av.x; As[ak + 1][ar] = av.y;
        As[ak + 2][ar] = av.z; As[ak + 3][ar] = av.w;
        if (TB) {
            float4 bv = *(const float4*)(Bp + ar * ldb + k0 + ak);
            Bs[ak + 0][ar] = bv.x; Bs[ak + 1][ar] = bv.y;
            Bs[ak + 2][ar] = bv.z; Bs[ak + 3][ar] = bv.w;
        } else {
            *(float4*)&Bs[nk][nc] = *(const float4*)(Bp + (k0 + nk) * ldb + nc);
        }
        __syncthreads();
        #pragma unroll
        for (int kk = 0; kk < 16; kk++) {
            float4 a4 = *(const float4*)&As[kk][ty << 2];
            float4 b4 = *(const float4*)&Bs[kk][tx << 2];
            float aa[4] = {a4.x, a4.y, a4.z, a4.w};
            float bb[4] = {b4.x, b4.y, b4.z, b4.w};
            #pragma unroll
            for (int i = 0; i < 4; i++)
                #pragma unroll
                for (int j = 0; j < 4; j++)
                    acc[i][j] += aa[i] * bb[j];
        }
    }
    #pragma unroll
    for (int i = 0; i < 4; i++) {
        int r = (ty << 2) + i;
        #pragma unroll
        for (int j = 0; j < 4; j++) {
            int c = (tx << 2) + j;
            float v = acc[i][j];
            if (bias) v += bias[c];
            if (EPI >= 1) v = fmaxf(v, 0.0f);
            C[r * ldc + c] = v;
        }
    }
}

__global__ void __launch_bounds__(256) k_qproj(const float* __restrict__ pq,
                                               const float* __restrict__ Wq,
                                               const float* __restrict__ bq)
{
    int m = blockIdx.z, n0 = blockIdx.x * 64;
    gemm64<false, 0>(pq + m * B_ * D_, D_,
                     Wq + m * D_ * D_ + n0, D_,
                     g_q + m * B_ * D_ + n0, D_, D_, bq + m * D_ + n0);
}

__global__ void __launch_bounds__(256) k_qk(const float* __restrict__ Wk)
{
    int m = blockIdx.z >> 3, h = blockIdx.z & 7, n0 = blockIdx.x * 64;
    gemm64<true, 0>(g_q + m * B_ * D_ + h * HD_, D_,
                    Wk + m * D_ * D_ + n0 * D_ + h * HD_, D_,
                    g_qk + (m * H_ + h) * D_ + n0, MH_ * D_, HD_, nullptr);
}

__global__ void __launch_bounds__(256) k_scores(const float* __restrict__ key_in)
{
    int b = blockIdx.z, n0 = blockIdx.x * 64;
    gemm64<true, 0>(g_qk + b * MH_ * D_, D_,
                    key_in + (long)n0 * B_ * D_ + b * D_, B_ * D_,
                    g_w + b * MH_ * S_ + n0, S_, D_, nullptr);
}

__global__ void __launch_bounds__(256) k_softmax(const float* __restrict__ bk)
{
    int row = blockIdx.x * 8 + (threadIdx.x >> 5);
    int lane = threadIdx.x & 31;
    int b = row >> 6, mh = row & 63;
    int m = mh >> 3, h = mh & 7;
    const float* qp  = g_q + m * B_ * D_ + b * D_ + h * HD_;
    const float* bkp = bk + m * D_ + h * HD_;
    float bias = qp[lane] * bkp[lane] + qp[lane + 32] * bkp[lane + 32];
    #pragma unroll
    for (int o = 16; o; o >>= 1) bias += __shfl_xor_sync(0xffffffffu, bias, o);
    float* wrow = g_w + b * MH_ * S_ + mh * S_;
    float v[4], mx = -INFINITY;
    #pragma unroll
    for (int i = 0; i < 4; i++) {
        v[i] = (wrow[lane + 32 * i] + bias) * 0.125f;
        mx = fmaxf(mx, v[i]);
    }
    #pragma unroll
    for (int o = 16; o; o >>= 1) mx = fmaxf(mx, __shfl_xor_sync(0xffffffffu, mx, o));
    float sum = 0.0f;
    #pragma unroll
    for (int i = 0; i < 4; i++) { v[i] = __expf(v[i] - mx); sum += v[i]; }
    #pragma unroll
    for (int o = 16; o; o >>= 1) sum += __shfl_xor_sync(0xffffffffu, sum, o);
    float inv = 1.0f / sum;
    #pragma unroll
    for (int i = 0; i < 4; i++) wrow[lane + 32 * i] = v[i] * inv;
}

__global__ void __launch_bounds__(256) k_wv(const float* __restrict__ value_in)
{
    int b = blockIdx.z, n0 = blockIdx.x * 64;
    gemm64<false, 0>(g_w + b * MH_ * S_, S_,
                     value_in + b * D_ + n0, B_ * D_,
                     g_wv + b * MH_ * D_ + n0, D_, S_, nullptr);
}

__global__ void __launch_bounds__(256) k_ao(const float* __restrict__ Wv,
                                            const float* __restrict__ bv)
{
    int m = blockIdx.z >> 3, h = blockIdx.z & 7;
    gemm64<false, 0>(g_wv + (m * H_ + h) * D_, MH_ * D_,
                     Wv + m * D_ * D_ + h * HD_, D_,
                     g_ao + m * B_ * D_ + h * HD_, D_, D_, bv + m * D_ + h * HD_);
}

__global__ void __launch_bounds__(256) k_attnout(const float* __restrict__ Wo,
                                                 const float* __restrict__ bo)
{
    int m = blockIdx.z, n0 = blockIdx.x * 64;
    gemm64<false, 1>(g_ao + m * B_ * D_, D_,
                     Wo + m * D_ * D_ + n0, D_,
                     g_x + m * B_ * TWOD_ + n0, TWOD_, D_, bo + m * D_ + n0);
}

__global__ void __launch_bounds__(256) k_xfill(const float* __restrict__ ps)
{
    int i = blockIdx.x * 256 + threadIdx.x;
    if (i < M_ * B_ * D_) {
        int mb = i >> 9, d = i & (D_ - 1);
        g_x[mb * TWOD_ + D_ + d] = fmaxf(ps[i], 0.0f);
    }
}

__global__ void __launch_bounds__(128) k_final(const float* __restrict__ Wg2,
                                               const float* __restrict__ bg2,
                                               const float* __restrict__ pq,
                                               const float* __restrict__ pk,
                                               const float* __restrict__ pv,
                                               const float* __restrict__ ps,
                                               float* __restrict__ out)
{
    int z = blockIdx.x;
    int g = z >> 9, rem = z & 511;
    int m = rem >> 6, b = rem & 63;
    int gm = g * M_ + m;
    int tid = threadIdx.x, lane = tid & 31;
    const float* hg = g_hg + ((long)gm * B_ + b) * FF_;
    const float* wg = Wg2 + (long)gm * FF_;
    float s = 0.0f;
    for (int f = tid; f < FF_; f += 128) s += hg[f] * wg[f];
    #pragma unroll
    for (int o = 16; o; o >>= 1) s += __shfl_xor_sync(0xffffffffu, s, o);
    __shared__ float red[4];
    if (lane == 0) red[tid >> 5] = s;
    __syncthreads();
    float tot = red[0] + red[1] + red[2] + red[3];
    float gate = 1.0f / (1.0f + __expf(-(tot + bg2[gm])));
    const float* prevs[4] = {pq, pk, pv, ps};
    const float* pr = prevs[g] + ((long)m * B_ + b) * D_;
    const float* ob = g_o + ((long)gm * B_ + b) * D_;
    float* dst = out + (((long)((g + 1) & 3) * M_ + m) * B_ + b) * D_;
    for (int d = tid; d < D_; d += 128)
        dst[d] = gate * ob[d] + (1.0f - gate) * pr[d];
}

// ---------------- launch ----------------
extern "C" void kernel_launch(void* const* d_in, const int* in_sizes, int n_in,
                              void* d_out, int out_size)
{
    const float* prev_state = (const float*)d_in[0];
    const float* prev_query = (const float*)d_in[1];
    const float* prev_key   = (const float*)d_in[2];
    const float* prev_value = (const float*)d_in[3];
    const float* key_in     = (const float*)d_in[4];
    const float* value_in   = (const float*)d_in[5];
    const float* Wq  = (const float*)d_in[6];
    const float* bq  = (const float*)d_in[7];
    const float* Wk  = (const float*)d_in[8];
    const float* bk  = (const float*)d_in[9];
    const float* Wv  = (const float*)d_in[10];
    const float* bv  = (const float*)d_in[11];
    const float* Wo  = (const float*)d_in[12];
    const float* bo  = (const float*)d_in[13];
    const float* W1  = (const float*)d_in[14];
    const float* b1  = (const float*)d_in[15];
    const float* W2  = (const float*)d_in[16];
    const float* b2  = (const float*)d_in[17];
    const float* Wg1 = (const float*)d_in[18];
    const float* bg1 = (const float*)d_in[19];
    const float* Wg2 = (const float*)d_in[20];
    const float* bg2 = (const float*)d_in[21];
    float* out = (float*)d_out;

    k_qproj  <<<dim3(D_ / 64, 1, M_),      256>>>(prev_query, Wq, bq);
    k_qk     <<<dim3(D_ / 64, 1, M_ * H_), 256>>>(Wk);
    k_scores <<<dim3(S_ / 64, 1, B_),      256>>>(key_in);
    k_softmax<<<(B_ * MH_) / 8,            256>>>(bk);
    k_wv     <<<dim3(D_ / 64, 1, B_),      256>>>(value_in);
    k_ao     <<<dim3(1, 1, M_ * H_),       256>>>(Wv, bv);
    k_attnout<<<dim3(D_ / 64, 1, M_),      256>>>(Wo, bo);
    k_xfill  <<<(M_ * B_ * D_ + 255) / 256, 256>>>(prev_state);
    // h = relu(x @ W1 + b1), hg = relu(x @ Wg1 + bg1)  (FFMA2)
    k_pgemm<256, 1><<<dim3(FF_ / 256, 1, 32), 256>>>(
        W1, FF_, (long long)TWOD_ * FF_,
        1, TWOD_, (long long)B_ * TWOD_, 7,
        2, FF_, (long long)B_ * FF_, b1, FF_, TWOD_);
    k_pgemm<256, 1><<<dim3(FF_ / 256, 1, 32), 256>>>(
        Wg1, FF_, (long long)TWOD_ * FF_,
        1, TWOD_, (long long)B_ * TWOD_, 7,
        3, FF_, (long long)B_ * FF_, bg1, FF_, TWOD_);
    // o = tanh(relu(h @ W2 + b2))  (FFMA2)
    k_pgemm<128, 2><<<dim3(D_ / 128, 1, 32), 256>>>(
        W2, D_, (long long)FF_ * D_,
        3, FF_, (long long)B_ * FF_, -1,
        4, D_, (long long)B_ * D_, b2, D_, FF_);
    k_final  <<<4 * M_ * B_, 128>>>(Wg2, bg2, prev_query, prev_key,
                                    prev_value, prev_state, out);
}